// round 3
// baseline (speedup 1.0000x reference)
#include <cuda_runtime.h>

// Problem constants
#define BB   2
#define SS   2048
#define DIM_ 1024
#define HH   16
#define DH_  64
#define MM   (BB * SS)      // 4096
#define HD_  (HH * DH_)     // 1024

// Scratch (device globals: allocation-free rule)
__device__ float g_Q[BB * HH * SS * DH_];   // [B,H,S,DH]
__device__ float g_K[BB * HH * SS * DH_];
__device__ float g_V[BB * HH * SS * DH_];
__device__ float g_C[MM * HD_];             // ctx, [B,S,H*DH] row-major

// ---------------------------------------------------------------------------
// QKV projection GEMM: out = X @ W + b, scattered into [B,H,S,DH]
// grid: (N/128, M/128, 3)   block: 256
// ---------------------------------------------------------------------------
__global__ __launch_bounds__(256) void qkv_gemm(
    const float* __restrict__ X,
    const float* __restrict__ Wq, const float* __restrict__ bq,
    const float* __restrict__ Wk, const float* __restrict__ bk,
    const float* __restrict__ Wv, const float* __restrict__ bv)
{
    const int which = blockIdx.z;
    const float* W    = (which == 0) ? Wq : (which == 1) ? Wk : Wv;
    const float* bias = (which == 0) ? bq : (which == 1) ? bk : bv;
    float* out        = (which == 0) ? g_Q : (which == 1) ? g_K : g_V;

    __shared__ float As[16][128];
    __shared__ float Bs[16][132];

    const int tid = threadIdx.x;
    const int m0 = blockIdx.y * 128;
    const int n0 = blockIdx.x * 128;
    const int tx = tid & 15;
    const int ty = tid >> 4;

    float acc[8][8];
#pragma unroll
    for (int i = 0; i < 8; i++)
#pragma unroll
        for (int j = 0; j < 8; j++) acc[i][j] = 0.0f;

    for (int k0 = 0; k0 < DIM_; k0 += 16) {
        // A tile (128 x 16), stored transposed
#pragma unroll
        for (int v = 0; v < 2; v++) {
            int idx = tid + v * 256;
            int r = idx >> 2;
            int cv = (idx & 3) * 4;
            float4 a = *(const float4*)(X + (size_t)(m0 + r) * DIM_ + k0 + cv);
            As[cv + 0][r] = a.x;
            As[cv + 1][r] = a.y;
            As[cv + 2][r] = a.z;
            As[cv + 3][r] = a.w;
        }
        // B tile (16 x 128)
#pragma unroll
        for (int v = 0; v < 2; v++) {
            int idx = tid + v * 256;
            int r = idx >> 5;
            int cv = (idx & 31) * 4;
            *(float4*)&Bs[r][cv] = *(const float4*)(W + (size_t)(k0 + r) * HD_ + n0 + cv);
        }
        __syncthreads();

#pragma unroll
        for (int kk = 0; kk < 16; kk++) {
            float a[8], b[8];
            *(float4*)(a)     = *(float4*)&As[kk][ty * 8];
            *(float4*)(a + 4) = *(float4*)&As[kk][ty * 8 + 4];
            *(float4*)(b)     = *(float4*)&Bs[kk][tx * 8];
            *(float4*)(b + 4) = *(float4*)&Bs[kk][tx * 8 + 4];
#pragma unroll
            for (int i = 0; i < 8; i++)
#pragma unroll
                for (int j = 0; j < 8; j++) acc[i][j] += a[i] * b[j];
        }
        __syncthreads();
    }

    // Epilogue: scatter into [B,H,S,DH]
#pragma unroll
    for (int i = 0; i < 8; i++) {
        int m = m0 + ty * 8 + i;
        int b = m >> 11;        // / 2048
        int s = m & 2047;
#pragma unroll
        for (int j = 0; j < 8; j++) {
            int n = n0 + tx * 8 + j;
            int h = n >> 6;
            int d = n & 63;
            out[(((size_t)(b * HH + h)) * SS + s) * DH_ + d] = acc[i][j] + bias[n];
        }
    }
}

// ---------------------------------------------------------------------------
// Flash attention: per (b,h), q-tiles of 64, k-tiles of 64, online softmax.
// grid: (S/64, B*H)  block: 256, dynamic smem
// ---------------------------------------------------------------------------
#define QS_STRIDE 65
#define KS_STRIDE 65
#define VS_STRIDE 64
#define PS_STRIDE 65
#define ATTN_SMEM_FLOATS (64 * QS_STRIDE + 64 * KS_STRIDE + 64 * VS_STRIDE + 64 * PS_STRIDE + 64)
#define ATTN_SMEM_BYTES  (ATTN_SMEM_FLOATS * 4)

__global__ __launch_bounds__(256) void attn_kernel(const float* __restrict__ mask)
{
    extern __shared__ float sm[];
    float* Qs  = sm;
    float* Ks  = Qs + 64 * QS_STRIDE;
    float* Vs  = Ks + 64 * KS_STRIDE;
    float* Ps  = Vs + 64 * VS_STRIDE;
    float* msk = Ps + 64 * PS_STRIDE;

    const int tid = threadIdx.x;
    const int bh = blockIdx.y;          // b*H + h
    const int b = bh >> 4;
    const int h = bh & 15;
    const int q0 = blockIdx.x * 64;

    const float* Qg = g_Q + (size_t)bh * SS * DH_;
    const float* Kg = g_K + (size_t)bh * SS * DH_;
    const float* Vg = g_V + (size_t)bh * SS * DH_;

    const int tx = tid & 15;
    const int ty = tid >> 4;

    // Load & pre-scale Q tile (fold 1/sqrt(DH) = 0.125 into Q)
#pragma unroll
    for (int v = 0; v < 4; v++) {
        int idx = tid + v * 256;
        int r = idx >> 4;
        int c = (idx & 15) * 4;
        float4 q = *(const float4*)(Qg + (size_t)(q0 + r) * DH_ + c);
        Qs[r * QS_STRIDE + c + 0] = q.x * 0.125f;
        Qs[r * QS_STRIDE + c + 1] = q.y * 0.125f;
        Qs[r * QS_STRIDE + c + 2] = q.z * 0.125f;
        Qs[r * QS_STRIDE + c + 3] = q.w * 0.125f;
    }

    float m_i[4], l_i[4], o[4][4];
#pragma unroll
    for (int i = 0; i < 4; i++) {
        m_i[i] = -1e30f;
        l_i[i] = 0.0f;
#pragma unroll
        for (int j = 0; j < 4; j++) o[i][j] = 0.0f;
    }

    const float* qp[4];
#pragma unroll
    for (int i = 0; i < 4; i++) qp[i] = &Qs[(ty * 4 + i) * QS_STRIDE];

    for (int k0 = 0; k0 < SS; k0 += 64) {
        // Load K, V tiles + mask slice
#pragma unroll
        for (int v = 0; v < 4; v++) {
            int idx = tid + v * 256;
            int r = idx >> 4;
            int c = (idx & 15) * 4;
            float4 kq = *(const float4*)(Kg + (size_t)(k0 + r) * DH_ + c);
            Ks[r * KS_STRIDE + c + 0] = kq.x;
            Ks[r * KS_STRIDE + c + 1] = kq.y;
            Ks[r * KS_STRIDE + c + 2] = kq.z;
            Ks[r * KS_STRIDE + c + 3] = kq.w;
            float4 vq = *(const float4*)(Vg + (size_t)(k0 + r) * DH_ + c);
            *(float4*)&Vs[r * VS_STRIDE + c] = vq;
        }
        if (tid < 64) msk[tid] = mask[b * SS + k0 + tid];
        __syncthreads();

        // Scores S = (Q*0.125) @ K^T  (4x4 per thread)
        float s[4][4];
#pragma unroll
        for (int i = 0; i < 4; i++)
#pragma unroll
            for (int j = 0; j < 4; j++) s[i][j] = 0.0f;

        const float* kp[4];
#pragma unroll
        for (int j = 0; j < 4; j++) kp[j] = &Ks[(tx * 4 + j) * KS_STRIDE];

#pragma unroll 4
        for (int kk = 0; kk < 64; kk++) {
            float a0 = qp[0][kk], a1 = qp[1][kk], a2 = qp[2][kk], a3 = qp[3][kk];
            float b0 = kp[0][kk], b1 = kp[1][kk], b2 = kp[2][kk], b3 = kp[3][kk];
            s[0][0] += a0 * b0; s[0][1] += a0 * b1; s[0][2] += a0 * b2; s[0][3] += a0 * b3;
            s[1][0] += a1 * b0; s[1][1] += a1 * b1; s[1][2] += a1 * b2; s[1][3] += a1 * b3;
            s[2][0] += a2 * b0; s[2][1] += a2 * b1; s[2][2] += a2 * b2; s[2][3] += a2 * b3;
            s[3][0] += a3 * b0; s[3][1] += a3 * b1; s[3][2] += a3 * b2; s[3][3] += a3 * b3;
        }

        // Apply mask + online softmax (rows owned by 16 tx-threads, width-16 reduce)
        float mk[4];
#pragma unroll
        for (int j = 0; j < 4; j++) mk[j] = 1.0e6f * (1.0f - msk[tx * 4 + j]);

#pragma unroll
        for (int i = 0; i < 4; i++) {
#pragma unroll
            for (int j = 0; j < 4; j++) s[i][j] -= mk[j];
            float mx = fmaxf(fmaxf(s[i][0], s[i][1]), fmaxf(s[i][2], s[i][3]));
#pragma unroll
            for (int off = 8; off > 0; off >>= 1)
                mx = fmaxf(mx, __shfl_xor_sync(0xffffffffu, mx, off, 16));
            float mnew = fmaxf(m_i[i], mx);
            float corr = __expf(m_i[i] - mnew);
            m_i[i] = mnew;
            float ssum = 0.0f;
#pragma unroll
            for (int j = 0; j < 4; j++) {
                float p = __expf(s[i][j] - mnew);
                Ps[(ty * 4 + i) * PS_STRIDE + tx * 4 + j] = p;
                ssum += p;
            }
#pragma unroll
            for (int off = 8; off > 0; off >>= 1)
                ssum += __shfl_xor_sync(0xffffffffu, ssum, off, 16);
            l_i[i] = l_i[i] * corr + ssum;
#pragma unroll
            for (int j = 0; j < 4; j++) o[i][j] *= corr;
        }
        __syncthreads();

        // O += P @ V  (thread owns rows ty*4+i, d-cols tx*4+j)
#pragma unroll 4
        for (int c = 0; c < 64; c++) {
            float4 v = *(const float4*)&Vs[c * VS_STRIDE + tx * 4];
#pragma unroll
            for (int i = 0; i < 4; i++) {
                float p = Ps[(ty * 4 + i) * PS_STRIDE + c];
                o[i][0] += p * v.x;
                o[i][1] += p * v.y;
                o[i][2] += p * v.z;
                o[i][3] += p * v.w;
            }
        }
        __syncthreads();
    }

    // Write ctx into [B,S,H*DH]
#pragma unroll
    for (int i = 0; i < 4; i++) {
        int r = q0 + ty * 4 + i;
        float inv = 1.0f / l_i[i];
#pragma unroll
        for (int j = 0; j < 4; j++) {
            g_C[((size_t)(b * SS + r)) * HD_ + h * DH_ + tx * 4 + j] = o[i][j] * inv;
        }
    }
}

// ---------------------------------------------------------------------------
// Output projection: out = ctx @ Wo + bo (row-major out)
// grid: (8, 32)  block: 256
// ---------------------------------------------------------------------------
__global__ __launch_bounds__(256) void out_gemm(
    const float* __restrict__ Wo, const float* __restrict__ bo,
    float* __restrict__ out)
{
    __shared__ float As[16][128];
    __shared__ float Bs[16][132];

    const int tid = threadIdx.x;
    const int m0 = blockIdx.y * 128;
    const int n0 = blockIdx.x * 128;
    const int tx = tid & 15;
    const int ty = tid >> 4;

    float acc[8][8];
#pragma unroll
    for (int i = 0; i < 8; i++)
#pragma unroll
        for (int j = 0; j < 8; j++) acc[i][j] = 0.0f;

    for (int k0 = 0; k0 < HD_; k0 += 16) {
#pragma unroll
        for (int v = 0; v < 2; v++) {
            int idx = tid + v * 256;
            int r = idx >> 2;
            int cv = (idx & 3) * 4;
            float4 a = *(const float4*)(g_C + (size_t)(m0 + r) * HD_ + k0 + cv);
            As[cv + 0][r] = a.x;
            As[cv + 1][r] = a.y;
            As[cv + 2][r] = a.z;
            As[cv + 3][r] = a.w;
        }
#pragma unroll
        for (int v = 0; v < 2; v++) {
            int idx = tid + v * 256;
            int r = idx >> 5;
            int cv = (idx & 31) * 4;
            *(float4*)&Bs[r][cv] = *(const float4*)(Wo + (size_t)(k0 + r) * DIM_ + n0 + cv);
        }
        __syncthreads();

#pragma unroll
        for (int kk = 0; kk < 16; kk++) {
            float a[8], b[8];
            *(float4*)(a)     = *(float4*)&As[kk][ty * 8];
            *(float4*)(a + 4) = *(float4*)&As[kk][ty * 8 + 4];
            *(float4*)(b)     = *(float4*)&Bs[kk][tx * 8];
            *(float4*)(b + 4) = *(float4*)&Bs[kk][tx * 8 + 4];
#pragma unroll
            for (int i = 0; i < 8; i++)
#pragma unroll
                for (int j = 0; j < 8; j++) acc[i][j] += a[i] * b[j];
        }
        __syncthreads();
    }

#pragma unroll
    for (int i = 0; i < 8; i++) {
        int m = m0 + ty * 8 + i;
#pragma unroll
        for (int j = 0; j < 8; j++) {
            int n = n0 + tx * 8 + j;
            out[(size_t)m * DIM_ + n] = acc[i][j] + bo[n];
        }
    }
}

// ---------------------------------------------------------------------------
extern "C" void kernel_launch(void* const* d_in, const int* in_sizes, int n_in,
                              void* d_out, int out_size)
{
    const float* X    = (const float*)d_in[0];
    const float* mask = (const float*)d_in[1];
    const float* Wq   = (const float*)d_in[2];
    const float* bq   = (const float*)d_in[3];
    const float* Wk   = (const float*)d_in[4];
    const float* bk   = (const float*)d_in[5];
    const float* Wv   = (const float*)d_in[6];
    const float* bv   = (const float*)d_in[7];
    const float* Wo   = (const float*)d_in[8];
    const float* bo   = (const float*)d_in[9];
    float* out        = (float*)d_out;

    cudaFuncSetAttribute(attn_kernel,
                         cudaFuncAttributeMaxDynamicSharedMemorySize,
                         ATTN_SMEM_BYTES);

    qkv_gemm<<<dim3(HD_ / 128, MM / 128, 3), 256>>>(X, Wq, bq, Wk, bk, Wv, bv);
    attn_kernel<<<dim3(SS / 64, BB * HH), 256, ATTN_SMEM_BYTES>>>(mask);
    out_gemm<<<dim3(DIM_ / 128, MM / 128), 256>>>(Wo, bo, out);
}

// round 11
// speedup vs baseline: 2.6533x; 2.6533x over previous
#include <cuda_runtime.h>
#include <cstdint>

// Problem constants
#define BB   2
#define SS_  2048
#define DIM_ 1024
#define HH   16
#define DH_  64
#define MM   (BB * SS_)     // 4096
#define HD_  (HH * DH_)     // 1024

// Scratch (device globals: allocation-free rule)
__device__ float g_Q[BB * HH * SS_ * DH_];   // [B,H,S,DH]
__device__ float g_K[BB * HH * SS_ * DH_];
__device__ float g_V[BB * HH * SS_ * DH_];
__device__ float g_C[MM * HD_];              // ctx, [B,S,H*DH] row-major

// ---------------------------------------------------------------------------
// Helpers
// ---------------------------------------------------------------------------
__device__ __forceinline__ uint32_t f2tf32(float x) {
    uint32_t u;
    asm("cvt.rna.tf32.f32 %0, %1;" : "=r"(u) : "f"(x));
    return u;
}

// D = A(16x8 tf32) * B(8x8 tf32) + D, fp32 accumulate
__device__ __forceinline__ void mma_tf32(float* c, const uint32_t* a, const uint32_t* b) {
    asm volatile(
        "mma.sync.aligned.m16n8k8.row.col.f32.tf32.tf32.f32 "
        "{%0,%1,%2,%3}, {%4,%5,%6,%7}, {%8,%9}, {%0,%1,%2,%3};"
        : "+f"(c[0]), "+f"(c[1]), "+f"(c[2]), "+f"(c[3])
        : "r"(a[0]), "r"(a[1]), "r"(a[2]), "r"(a[3]), "r"(b[0]), "r"(b[1]));
}

// ===========================================================================
// tf32 mma.sync GEMM: C[M,N] = A[M,1024] @ W[1024,N] + bias
//   CTA tile 128x128, 8 warps of 64x32, K-chunk 32.
//   MODE 0: qkv (blockIdx.z selects W/bias; scatter into g_Q/g_K/g_V [B,H,S,DH])
//   MODE 1: out projection (A = g_C, W = W0 = Wo, bias = b0 = bo, row-major out)
// ===========================================================================
#define GAS 36    // As stride (u32)
#define GBS 132   // Bs stride (u32)

template <int MODE>
__global__ __launch_bounds__(256) void gemm_mma(
    const float* __restrict__ Ain,
    const float* __restrict__ W0, const float* __restrict__ b0,
    const float* __restrict__ W1, const float* __restrict__ b1,
    const float* __restrict__ W2, const float* __restrict__ b2,
    float* __restrict__ outp)
{
    __shared__ uint32_t As[128 * GAS];   // [m][k] tf32
    __shared__ uint32_t Bs[32 * GBS];    // [k][n] tf32

    const int tid  = threadIdx.x;
    const int wid  = tid >> 5;
    const int lane = tid & 31;
    const int g    = lane >> 2;   // 0..7
    const int q    = lane & 3;    // 0..3
    const int m0 = blockIdx.y * 128;
    const int n0 = blockIdx.x * 128;
    const int wm = (wid >> 2) * 64;   // warp m-offset (0 or 64)
    const int wn = (wid & 3) * 32;    // warp n-offset (0,32,64,96)

    const float* A;
    const float* W;
    const float* bias;
    float* op;
    if (MODE == 0) {
        A = Ain;
        int z = blockIdx.z;
        W    = (z == 0) ? W0 : (z == 1) ? W1 : W2;
        bias = (z == 0) ? b0 : (z == 1) ? b1 : b2;
        op   = nullptr;
    } else {
        A = g_C; W = W0; bias = b0; op = outp;   // launch passes W0=Wo, b0=bo
    }

    float acc[4][4][4];
#pragma unroll
    for (int mt = 0; mt < 4; mt++)
#pragma unroll
        for (int nt = 0; nt < 4; nt++)
#pragma unroll
            for (int j = 0; j < 4; j++) acc[mt][nt][j] = 0.0f;

    for (int k0 = 0; k0 < DIM_; k0 += 32) {
        // A tile: 128 x 32
#pragma unroll
        for (int t = 0; t < 4; t++) {
            int idx = tid + t * 256;
            int r = idx >> 3;
            int c4 = (idx & 7) * 4;
            float4 v = *(const float4*)(A + (size_t)(m0 + r) * DIM_ + k0 + c4);
            uint32_t* p = &As[r * GAS + c4];
            p[0] = f2tf32(v.x); p[1] = f2tf32(v.y);
            p[2] = f2tf32(v.z); p[3] = f2tf32(v.w);
        }
        // B tile: 32 x 128 (direct copy, no transpose)
#pragma unroll
        for (int t = 0; t < 4; t++) {
            int idx = tid + t * 256;
            int kk = idx >> 5;
            int n4 = (idx & 31) * 4;
            float4 w = *(const float4*)(W + (size_t)(k0 + kk) * 1024 + n0 + n4);
            uint32_t* p = &Bs[kk * GBS + n4];
            p[0] = f2tf32(w.x); p[1] = f2tf32(w.y);
            p[2] = f2tf32(w.z); p[3] = f2tf32(w.w);
        }
        __syncthreads();

#pragma unroll
        for (int ks = 0; ks < 32; ks += 8) {
            uint32_t a[4][4], bfr[4][2];
#pragma unroll
            for (int mt = 0; mt < 4; mt++) {
                int r = wm + mt * 16 + g;
                a[mt][0] = As[r * GAS + ks + q];
                a[mt][1] = As[(r + 8) * GAS + ks + q];
                a[mt][2] = As[r * GAS + ks + q + 4];
                a[mt][3] = As[(r + 8) * GAS + ks + q + 4];
            }
#pragma unroll
            for (int nt = 0; nt < 4; nt++) {
                int n = wn + nt * 8 + g;
                bfr[nt][0] = Bs[(ks + q) * GBS + n];
                bfr[nt][1] = Bs[(ks + q + 4) * GBS + n];
            }
#pragma unroll
            for (int mt = 0; mt < 4; mt++)
#pragma unroll
                for (int nt = 0; nt < 4; nt++)
                    mma_tf32(acc[mt][nt], a[mt], bfr[nt]);
        }
        __syncthreads();
    }

    // Epilogue: C frag (rows g,g+8 ; cols 2q,2q+1) + bias, scatter/store
#pragma unroll
    for (int mt = 0; mt < 4; mt++) {
#pragma unroll
        for (int nt = 0; nt < 4; nt++) {
            int n = n0 + wn + nt * 8 + 2 * q;
            float bn0 = bias[n], bn1 = bias[n + 1];
            int mA = m0 + wm + mt * 16 + g;
            int mB = mA + 8;
            float2 v0 = make_float2(acc[mt][nt][0] + bn0, acc[mt][nt][1] + bn1);
            float2 v1 = make_float2(acc[mt][nt][2] + bn0, acc[mt][nt][3] + bn1);
            if (MODE == 0) {
                float* dst = (blockIdx.z == 0) ? g_Q : (blockIdx.z == 1) ? g_K : g_V;
                int h = n >> 6, d = n & 63;
                int bA = mA >> 11, sA = mA & 2047;
                int bW = mB >> 11, sB = mB & 2047;
                *(float2*)(dst + ((((size_t)(bA * HH + h)) * SS_ + sA) << 6) + d) = v0;
                *(float2*)(dst + ((((size_t)(bW * HH + h)) * SS_ + sB) << 6) + d) = v1;
            } else {
                *(float2*)(op + (size_t)mA * DIM_ + n) = v0;
                *(float2*)(op + (size_t)mB * DIM_ + n) = v1;
            }
        }
    }
}

// ===========================================================================
// Flash attention with tf32 mma.sync
//   q-tile 128 per CTA, 8 warps x 16 q-rows, key-tile 64, DH=64.
//   Per warp: S = 16x64 (8 n-subtiles), O = 16x64. P is warp-private in SMEM.
// ===========================================================================
#define AQS 68
#define AKS 68
#define AVS 68
#define APS 68
#define ATTN_SMEM_U32 (128 * AQS + 64 * AKS + 64 * AVS + 128 * APS + 64)
#define ATTN_SMEM_BYTES (ATTN_SMEM_U32 * 4)

__global__ __launch_bounds__(256) void attn_mma(const float* __restrict__ mask)
{
    extern __shared__ uint32_t sm[];
    uint32_t* Qs = sm;                      // [128][AQS] tf32 (prescaled)
    uint32_t* Ks = Qs + 128 * AQS;          // [64][AKS]  tf32  (rows = key)
    uint32_t* Vs = Ks + 64 * AKS;           // [64][AVS]  tf32  (rows = key)
    uint32_t* Ps = Vs + 64 * AVS;           // [128][APS] tf32
    float*   msk = (float*)(Ps + 128 * APS);

    const int tid  = threadIdx.x;
    const int wid  = tid >> 5;
    const int lane = tid & 31;
    const int g    = lane >> 2;
    const int q    = lane & 3;
    const int bh = blockIdx.y;
    const int b  = bh >> 4;
    const int h  = bh & 15;
    const int q0 = blockIdx.x * 128;
    const int wq = wid * 16;

    const float* Qg = g_Q + (size_t)bh * SS_ * DH_;
    const float* Kg = g_K + (size_t)bh * SS_ * DH_;
    const float* Vg = g_V + (size_t)bh * SS_ * DH_;

    // Load Q tile (128 x 64), fold 1/sqrt(DH)=0.125
#pragma unroll
    for (int t = 0; t < 8; t++) {
        int idx = tid + t * 256;
        int r = idx >> 4;
        int c4 = (idx & 15) * 4;
        float4 v = *(const float4*)(Qg + (size_t)(q0 + r) * DH_ + c4);
        uint32_t* p = &Qs[r * AQS + c4];
        p[0] = f2tf32(v.x * 0.125f); p[1] = f2tf32(v.y * 0.125f);
        p[2] = f2tf32(v.z * 0.125f); p[3] = f2tf32(v.w * 0.125f);
    }

    float O[8][4];
#pragma unroll
    for (int nt = 0; nt < 8; nt++)
#pragma unroll
        for (int j = 0; j < 4; j++) O[nt][j] = 0.0f;
    float m0r = -1e30f, m1r = -1e30f, l0 = 0.0f, l1 = 0.0f;

    __syncthreads();

    for (int k0 = 0; k0 < SS_; k0 += 64) {
        // Load K, V tiles (64 x 64 each) + mask slice
#pragma unroll
        for (int t = 0; t < 4; t++) {
            int idx = tid + t * 256;
            int r = idx >> 4;
            int c4 = (idx & 15) * 4;
            float4 kv = *(const float4*)(Kg + (size_t)(k0 + r) * DH_ + c4);
            uint32_t* pk = &Ks[r * AKS + c4];
            pk[0] = f2tf32(kv.x); pk[1] = f2tf32(kv.y);
            pk[2] = f2tf32(kv.z); pk[3] = f2tf32(kv.w);
            float4 vv = *(const float4*)(Vg + (size_t)(k0 + r) * DH_ + c4);
            uint32_t* pv = &Vs[r * AVS + c4];
            pv[0] = f2tf32(vv.x); pv[1] = f2tf32(vv.y);
            pv[2] = f2tf32(vv.z); pv[3] = f2tf32(vv.w);
        }
        if (tid < 64) msk[tid] = mask[b * SS_ + k0 + tid];
        __syncthreads();

        // S = Q @ K^T  (per-warp 16 x 64)
        float s[8][4];
#pragma unroll
        for (int nt = 0; nt < 8; nt++)
#pragma unroll
            for (int j = 0; j < 4; j++) s[nt][j] = 0.0f;

#pragma unroll
        for (int ks = 0; ks < 64; ks += 8) {
            uint32_t a[4];
            a[0] = Qs[(wq + g) * AQS + ks + q];
            a[1] = Qs[(wq + g + 8) * AQS + ks + q];
            a[2] = Qs[(wq + g) * AQS + ks + q + 4];
            a[3] = Qs[(wq + g + 8) * AQS + ks + q + 4];
#pragma unroll
            for (int nt = 0; nt < 8; nt++) {
                uint32_t bb[2];
                bb[0] = Ks[(nt * 8 + g) * AKS + ks + q];
                bb[1] = Ks[(nt * 8 + g) * AKS + ks + q + 4];
                mma_tf32(s[nt], a, bb);
            }
        }

        // Mask + row max (rows g and g+8; this warp owns the full 64-key width)
        float mx0 = -1e30f, mx1 = -1e30f;
#pragma unroll
        for (int nt = 0; nt < 8; nt++) {
            int col = nt * 8 + 2 * q;
            float mk0 = 1.0e6f * (1.0f - msk[col]);
            float mk1 = 1.0e6f * (1.0f - msk[col + 1]);
            s[nt][0] -= mk0; s[nt][1] -= mk1;
            s[nt][2] -= mk0; s[nt][3] -= mk1;
            mx0 = fmaxf(mx0, fmaxf(s[nt][0], s[nt][1]));
            mx1 = fmaxf(mx1, fmaxf(s[nt][2], s[nt][3]));
        }
        mx0 = fmaxf(mx0, __shfl_xor_sync(0xffffffffu, mx0, 1));
        mx0 = fmaxf(mx0, __shfl_xor_sync(0xffffffffu, mx0, 2));
        mx1 = fmaxf(mx1, __shfl_xor_sync(0xffffffffu, mx1, 1));
        mx1 = fmaxf(mx1, __shfl_xor_sync(0xffffffffu, mx1, 2));

        float mn0 = fmaxf(m0r, mx0), mn1 = fmaxf(m1r, mx1);
        float c0 = __expf(m0r - mn0), c1 = __expf(m1r - mn1);
        m0r = mn0; m1r = mn1;

        float s0 = 0.0f, s1 = 0.0f;
#pragma unroll
        for (int nt = 0; nt < 8; nt++) {
            float p0 = __expf(s[nt][0] - mn0);
            float p1 = __expf(s[nt][1] - mn0);
            float p2 = __expf(s[nt][2] - mn1);
            float p3 = __expf(s[nt][3] - mn1);
            s0 += p0 + p1; s1 += p2 + p3;
            int col = nt * 8 + 2 * q;
            Ps[(wq + g) * APS + col]     = f2tf32(p0);
            Ps[(wq + g) * APS + col + 1] = f2tf32(p1);
            Ps[(wq + g + 8) * APS + col]     = f2tf32(p2);
            Ps[(wq + g + 8) * APS + col + 1] = f2tf32(p3);
            O[nt][0] *= c0; O[nt][1] *= c0;
            O[nt][2] *= c1; O[nt][3] *= c1;
        }
        s0 += __shfl_xor_sync(0xffffffffu, s0, 1);
        s0 += __shfl_xor_sync(0xffffffffu, s0, 2);
        s1 += __shfl_xor_sync(0xffffffffu, s1, 1);
        s1 += __shfl_xor_sync(0xffffffffu, s1, 2);
        l0 = l0 * c0 + s0;
        l1 = l1 * c1 + s1;

        __syncwarp();   // Ps rows [wq, wq+16) are warp-private; lane visibility only

        // O += P @ V  (k = key dim 64)
#pragma unroll
        for (int ks = 0; ks < 64; ks += 8) {
            uint32_t a[4];
            a[0] = Ps[(wq + g) * APS + ks + q];
            a[1] = Ps[(wq + g + 8) * APS + ks + q];
            a[2] = Ps[(wq + g) * APS + ks + q + 4];
            a[3] = Ps[(wq + g + 8) * APS + ks + q + 4];
#pragma unroll
            for (int nt = 0; nt < 8; nt++) {
                uint32_t bb[2];
                bb[0] = Vs[(ks + q) * AVS + nt * 8 + g];
                bb[1] = Vs[(ks + q + 4) * AVS + nt * 8 + g];
                mma_tf32(O[nt], a, bb);
            }
        }
        __syncthreads();   // protect Ks/Vs before next tile load
    }

    // Normalize and write ctx [B,S,H*DH]
    float inv0 = 1.0f / l0, inv1 = 1.0f / l1;
    int qr0 = q0 + wq + g;
    int qr1 = qr0 + 8;
#pragma unroll
    for (int nt = 0; nt < 8; nt++) {
        int d = nt * 8 + 2 * q;
        float2 v0 = make_float2(O[nt][0] * inv0, O[nt][1] * inv0);
        float2 v1 = make_float2(O[nt][2] * inv1, O[nt][3] * inv1);
        *(float2*)(g_C + ((size_t)(b * SS_ + qr0)) * HD_ + h * 64 + d) = v0;
        *(float2*)(g_C + ((size_t)(b * SS_ + qr1)) * HD_ + h * 64 + d) = v1;
    }
}

// ===========================================================================
extern "C" void kernel_launch(void* const* d_in, const int* in_sizes, int n_in,
                              void* d_out, int out_size)
{
    const float* X    = (const float*)d_in[0];
    const float* mask = (const float*)d_in[1];
    const float* Wq   = (const float*)d_in[2];
    const float* bq   = (const float*)d_in[3];
    const float* Wk   = (const float*)d_in[4];
    const float* bk   = (const float*)d_in[5];
    const float* Wv   = (const float*)d_in[6];
    const float* bv   = (const float*)d_in[7];
    const float* Wo   = (const float*)d_in[8];
    const float* bo   = (const float*)d_in[9];
    float* out        = (float*)d_out;

    cudaFuncSetAttribute(attn_mma, cudaFuncAttributeMaxDynamicSharedMemorySize,
                         ATTN_SMEM_BYTES);

    gemm_mma<0><<<dim3(HD_ / 128, MM / 128, 3), 256>>>(
        X, Wq, bq, Wk, bk, Wv, bv, nullptr);
    attn_mma<<<dim3(SS_ / 128, BB * HH), 256, ATTN_SMEM_BYTES>>>(mask);
    // FIX (root cause of R8/R9 IMA): MODE 1 reads W=W0, bias=b0 — pass Wo/bo
    // in those slots, NOT as Ain (which had made W=bo and bias=nullptr).
    gemm_mma<1><<<dim3(DIM_ / 128, MM / 128), 256>>>(
        nullptr, Wo, bo, nullptr, nullptr, nullptr, nullptr, out);
}